// round 2
// baseline (speedup 1.0000x reference)
#include <cuda_runtime.h>
#include <math.h>
#include <stdint.h>

// Problem constants
#define V_SIZE 50257
#define B_SIZE 8
#define S_SIZE 512
#define NUM_DRAFTS 4
#define DRAFT_LEN 8
#define NROWS 256              // NUM_DRAFTS*DRAFT_LEN*B = 4*8*8
#define NCHUNKS 8
#define CHUNK_SZ ((V_SIZE + NCHUNKS - 1) / NCHUNKS)

// threefry2x32 key for jax.random.key(42): (0, 42)
#define TF_KS0 0u
#define TF_KS1 42u
#define TF_KS2 (0x1BD11BDAu ^ TF_KS0 ^ TF_KS1)

// Scratch (device globals; no allocations allowed)
__device__ float g_max[B_SIZE];
__device__ float g_sum[B_SIZE];
__device__ unsigned long long g_best[NROWS];

__device__ __forceinline__ void tf_round(uint32_t &x0, uint32_t &x1, int r) {
    x0 += x1;
    x1 = __funnelshift_l(x1, x1, r);
    x1 ^= x0;
}

__device__ __forceinline__ uint2 threefry2x32(uint32_t x0, uint32_t x1) {
    x0 += TF_KS0; x1 += TF_KS1;
    tf_round(x0,x1,13); tf_round(x0,x1,15); tf_round(x0,x1,26); tf_round(x0,x1,6);
    x0 += TF_KS1; x1 += TF_KS2 + 1u;
    tf_round(x0,x1,17); tf_round(x0,x1,29); tf_round(x0,x1,16); tf_round(x0,x1,24);
    x0 += TF_KS2; x1 += TF_KS0 + 2u;
    tf_round(x0,x1,13); tf_round(x0,x1,15); tf_round(x0,x1,26); tf_round(x0,x1,6);
    x0 += TF_KS0; x1 += TF_KS1 + 3u;
    tf_round(x0,x1,17); tf_round(x0,x1,29); tf_round(x0,x1,16); tf_round(x0,x1,24);
    x0 += TF_KS1; x1 += TF_KS2 + 4u;
    tf_round(x0,x1,13); tf_round(x0,x1,15); tf_round(x0,x1,26); tf_round(x0,x1,6);
    x0 += TF_KS2; x1 += TF_KS0 + 5u;
    return make_uint2(x0, x1);
}

// Partitionable threefry random_bits (32-bit): counter i (< 2^32) ->
// threefry2x32(key, x0=hi(i)=0, x1=lo(i)=i), folded o.x ^ o.y.
__device__ __forceinline__ uint32_t tf_bits32(uint32_t i) {
    uint2 o = threefry2x32(0u, i);
    return o.x ^ o.y;
}

// jax uniform(minval=tiny, maxval=1) -> gumbel = -log(-log(u))
__device__ __forceinline__ float gumbel_from_bits(uint32_t bits) {
    float f = __uint_as_float((bits >> 9) | 0x3f800000u) - 1.0f;
    float u = fmaxf(f, 1.17549435e-38f);   // equals f*(1-tiny)+tiny then max(tiny,.) in f32
    return -logf(-logf(u));
}

// Pack (value, index) into u64 so that max() gives argmax with FIRST-index ties
// (jnp.argmax returns the first occurrence of the max).
__device__ __forceinline__ unsigned long long pack_vi(float val, int idx) {
    uint32_t b = __float_as_uint(val);
    uint32_t mono = (b & 0x80000000u) ? ~b : (b | 0x80000000u);
    return ((unsigned long long)mono << 32) | (uint32_t)(~(uint32_t)idx);
}

// ---------------------------------------------------------------------------
// Kernel A: per-batch softmax stats over logits[b, S-1, :], plus g_best init.
// grid = 9 blocks x 256 threads (block 8 zeroes g_best).
// ---------------------------------------------------------------------------
__global__ void spec_stats_kernel(const float* __restrict__ logits) {
    int blk = blockIdx.x;
    int t = threadIdx.x;
    if (blk == B_SIZE) {
        g_best[t] = 0ull;   // below any finite packed encoding
        return;
    }
    const float* last = logits + ((size_t)blk * S_SIZE + (S_SIZE - 1)) * V_SIZE;
    __shared__ float sh[256];
    float m = -INFINITY;
    for (int v = t; v < V_SIZE; v += 256) m = fmaxf(m, last[v]);
    sh[t] = m; __syncthreads();
    for (int s = 128; s; s >>= 1) {
        if (t < s) sh[t] = fmaxf(sh[t], sh[t + s]);
        __syncthreads();
    }
    float mx = sh[0];
    __syncthreads();
    float acc = 0.0f;
    for (int v = t; v < V_SIZE; v += 256) acc += expf(last[v] - mx);
    sh[t] = acc; __syncthreads();
    for (int s = 128; s; s >>= 1) {
        if (t < s) sh[t] += sh[t + s];
        __syncthreads();
    }
    if (t == 0) { g_max[blk] = mx; g_sum[blk] = sh[0]; }
}

// ---------------------------------------------------------------------------
// Kernel B: gumbel-argmax, partitionable threefry stream.
// grid = (NCHUNKS, NROWS); block (chunk c, row r) scans v in chunk c of
// row r's noise: counter i = r*V + v.
// ---------------------------------------------------------------------------
__global__ void __launch_bounds__(256) spec_argmax_kernel(const float* __restrict__ logits) {
    const int r = blockIdx.y;              // 0..255: flattened (k,l,b)
    const int b = r & 7;
    const float* last = logits + ((size_t)b * S_SIZE + (S_SIZE - 1)) * V_SIZE;

    const int begin = blockIdx.x * CHUNK_SZ;
    const int end   = min(V_SIZE, begin + CHUNK_SZ);
    const uint32_t base = (uint32_t)r * (uint32_t)V_SIZE;

    float best = -INFINITY;
    int idx = 0;

    #pragma unroll 2
    for (int v = begin + threadIdx.x; v < end; v += 256) {
        uint32_t bits = tf_bits32(base + (uint32_t)v);
        float g = gumbel_from_bits(bits) + __ldg(last + v);
        if (g > best) { best = g; idx = v; }   // ascending v: > keeps first max
    }

    __shared__ unsigned long long sh[256];
    int t = threadIdx.x;
    sh[t] = pack_vi(best, idx);
    __syncthreads();
    for (int s = 128; s; s >>= 1) {
        if (t < s) {
            unsigned long long a = sh[t + s];
            if (a > sh[t]) sh[t] = a;
        }
        __syncthreads();
    }
    if (t == 0) atomicMax(&g_best[r], sh[0]);
}

// ---------------------------------------------------------------------------
// Kernel C: finalize. 1 block x 256 threads; t enumerates (b,k,l) in the
// draft_tokens output order b*32 + k*8 + l.
// Output layout (float32, concatenated tuple, 808 elements):
//   [0,256)   draft_tokens  (B,K,L)
//   [256,512) draft_probs
//   [512,768) accepted_mask (0/1)
//   [768,800) acceptance_ratio (B,K)
//   [800,808) best_draft_idx (B)
// ---------------------------------------------------------------------------
__global__ void spec_finalize_kernel(const float* __restrict__ logits,
                                     float* __restrict__ out) {
    int t = threadIdx.x;
    int b = t >> 5;
    int k = (t >> 3) & 3;
    int l = t & 7;
    int row = ((k * DRAFT_LEN + l) << 3) + b;   // flattened (k,l,b)

    unsigned long long pk = g_best[row];
    int tok = (int)(~(uint32_t)(pk & 0xFFFFFFFFull));

    const float* last = logits + ((size_t)b * S_SIZE + (S_SIZE - 1)) * V_SIZE;
    float p = expf(last[tok] - g_max[b]) / g_sum[b];
    float m = (p >= 0.8f) ? 1.0f : 0.0f;

    out[t]       = (float)tok;   // token ids < 2^24: exact in f32
    out[256 + t] = p;
    out[512 + t] = m;

    __shared__ float sp[256];
    __shared__ float sm[256];
    __shared__ float meanp[32];
    sp[t] = p; sm[t] = m;
    __syncthreads();

    if ((t & 7) == 0) {
        float ps = 0.0f, ms = 0.0f;
        #pragma unroll
        for (int i = 0; i < 8; i++) { ps += sp[t + i]; ms += sm[t + i]; }
        int bk = t >> 3;                 // = b*4 + k
        out[768 + bk] = ms * 0.125f;     // acceptance_ratio
        meanp[bk] = ps;                  // scale irrelevant to argmax
    }
    __syncthreads();

    if (t < B_SIZE) {
        float bv = meanp[t * 4];
        int bi = 0;
        #pragma unroll
        for (int kk = 1; kk < 4; kk++) {
            float vv = meanp[t * 4 + kk];
            if (vv > bv) { bv = vv; bi = kk; }   // strict >: first max wins
        }
        out[800 + t] = (float)bi;
    }
}

extern "C" void kernel_launch(void* const* d_in, const int* in_sizes, int n_in,
                              void* d_out, int out_size) {
    // metadata order: hidden_states, logits, verifier_logits.
    // Only logits[:, -1, :] is live in the reference.
    const float* logits = (const float*)d_in[1];
    float* out = (float*)d_out;

    spec_stats_kernel<<<B_SIZE + 1, 256>>>(logits);
    spec_argmax_kernel<<<dim3(NCHUNKS, NROWS), 256>>>(logits);
    spec_finalize_kernel<<<1, 256>>>(logits, out);
}

// round 3
// speedup vs baseline: 1.2072x; 1.2072x over previous
#include <cuda_runtime.h>
#include <math.h>
#include <stdint.h>

// Problem constants
#define V_SIZE 50257
#define B_SIZE 8
#define S_SIZE 512
#define NUM_DRAFTS 4
#define DRAFT_LEN 8
#define NROWS 256                         // K*L*B = 4*8*8
#define NCHUNKS 8                         // argmax chunks per row
#define CHUNK_SZ ((V_SIZE + NCHUNKS - 1) / NCHUNKS)
#define SCHUNKS 16                        // exp-table chunks per batch row
#define SCHUNK_SZ ((V_SIZE + SCHUNKS - 1) / SCHUNKS)

// threefry2x32 key for jax.random.key(42): (0, 42)
#define TF_KS0 0u
#define TF_KS1 42u
#define TF_KS2 (0x1BD11BDAu ^ TF_KS0 ^ TF_KS1)

// Scratch (device globals; allocations are forbidden)
__device__ float g_E[B_SIZE][V_SIZE];          // exp(last_logits)
__device__ float g_sumpart[B_SIZE][SCHUNKS];   // partial exp-sums
__device__ float g_pE[NROWS * NCHUNKS];        // per-(row,chunk) best numerator
__device__ float g_pe[NROWS * NCHUNKS];        // per-(row,chunk) best denominator
__device__ int   g_pi[NROWS * NCHUNKS];        // per-(row,chunk) best index

__device__ __forceinline__ void tf_round(uint32_t &x0, uint32_t &x1, int r) {
    x0 += x1;
    x1 = __funnelshift_l(x1, x1, r);
    x1 ^= x0;
}

// Partitionable threefry random_bits (32-bit): counter i (< 2^32) ->
// threefry2x32(key=(0,42), x0=0, x1=i), folded o.x ^ o.y.
__device__ __forceinline__ uint32_t tf_bits32(uint32_t i) {
    uint32_t x0 = TF_KS0, x1 = i + TF_KS1;
    tf_round(x0,x1,13); tf_round(x0,x1,15); tf_round(x0,x1,26); tf_round(x0,x1,6);
    x0 += TF_KS1; x1 += TF_KS2 + 1u;
    tf_round(x0,x1,17); tf_round(x0,x1,29); tf_round(x0,x1,16); tf_round(x0,x1,24);
    x0 += TF_KS2; x1 += TF_KS0 + 2u;
    tf_round(x0,x1,13); tf_round(x0,x1,15); tf_round(x0,x1,26); tf_round(x0,x1,6);
    x0 += TF_KS0; x1 += TF_KS1 + 3u;
    tf_round(x0,x1,17); tf_round(x0,x1,29); tf_round(x0,x1,16); tf_round(x0,x1,24);
    x0 += TF_KS1; x1 += TF_KS2 + 4u;
    tf_round(x0,x1,13); tf_round(x0,x1,15); tf_round(x0,x1,26); tf_round(x0,x1,6);
    x0 += TF_KS2; x1 += TF_KS0 + 5u;
    return x0 ^ x1;
}

// ---------------------------------------------------------------------------
// Kernel A: E[b][v] = expf(logits[b, S-1, v]) + per-block partial exp-sums.
// grid = (B_SIZE, SCHUNKS) x 256 threads.
// ---------------------------------------------------------------------------
__global__ void __launch_bounds__(256) spec_exp_kernel(const float* __restrict__ logits) {
    const int b = blockIdx.x;
    const float* last = logits + ((size_t)b * S_SIZE + (S_SIZE - 1)) * V_SIZE;
    const int begin = blockIdx.y * SCHUNK_SZ;
    const int end   = min(V_SIZE, begin + SCHUNK_SZ);

    float acc = 0.0f;
    for (int v = begin + threadIdx.x; v < end; v += 256) {
        float e = expf(__ldg(last + v));
        g_E[b][v] = e;
        acc += e;
    }
    __shared__ float sh[256];
    int t = threadIdx.x;
    sh[t] = acc; __syncthreads();
    for (int s = 128; s; s >>= 1) {
        if (t < s) sh[t] += sh[t + s];
        __syncthreads();
    }
    if (t == 0) g_sumpart[b][blockIdx.y] = sh[0];
}

// ---------------------------------------------------------------------------
// Kernel B: gumbel-argmax in ratio domain.
//   score(v) = exp(lv)/e_v, e_v = -log(u_v);  argmax score == argmax (lv + g).
// Best kept as fraction (bestE, beste); compare E*beste > bestE*e (no div).
// grid = (NCHUNKS, NROWS) x 256 threads; counter i = r*V + v (partitionable).
// ---------------------------------------------------------------------------
__global__ void __launch_bounds__(256) spec_argmax_kernel() {
    const int r = blockIdx.y;              // flattened (k,l,b); b = r & 7
    const int b = r & 7;
    const float* __restrict__ Erow = g_E[b];

    const int begin = blockIdx.x * CHUNK_SZ;
    const int end   = min(V_SIZE, begin + CHUNK_SZ);
    const uint32_t base = (uint32_t)r * (uint32_t)V_SIZE;

    float bestE = 0.0f, beste = 1.0f;      // score 0: any real candidate beats it
    int idx = 0;

    #pragma unroll 4
    for (int v = begin + threadIdx.x; v < end; v += 256) {
        uint32_t bits = tf_bits32(base + (uint32_t)v);
        float f = __uint_as_float((bits >> 9) | 0x3f800000u) - 1.0f;
        float u = fmaxf(f, 1.17549435e-38f);       // jax uniform(minval=tiny)
        float e = -logf(u);                        // e > 0
        float E = __ldg(Erow + v);
        // ascending v with strict >: first max wins (jnp.argmax tie rule)
        if (E * beste > bestE * e) { bestE = E; beste = e; idx = v; }
    }

    __shared__ float sE[256];
    __shared__ float se[256];
    __shared__ int   si[256];
    int t = threadIdx.x;
    sE[t] = bestE; se[t] = beste; si[t] = idx;
    __syncthreads();
    for (int s = 128; s; s >>= 1) {
        if (t < s) {
            float a = sE[t + s] * se[t];
            float c = sE[t] * se[t + s];
            // strictly better, or exact tie with smaller index
            if (a > c || (a == c && si[t + s] < si[t])) {
                sE[t] = sE[t + s]; se[t] = se[t + s]; si[t] = si[t + s];
            }
        }
        __syncthreads();
    }
    if (t == 0) {
        int slot = r * NCHUNKS + blockIdx.x;
        g_pE[slot] = sE[0];
        g_pe[slot] = se[0];
        g_pi[slot] = si[0];
    }
}

// ---------------------------------------------------------------------------
// Kernel C: finalize. 1 block x 256 threads; t enumerates (b,k,l) in
// draft_tokens output order b*32 + k*8 + l.
// Output layout (float32, concatenated tuple, 808 elements):
//   [0,256)   draft_tokens  (B,K,L)
//   [256,512) draft_probs
//   [512,768) accepted_mask (0/1)
//   [768,800) acceptance_ratio (B,K)
//   [800,808) best_draft_idx (B)
// ---------------------------------------------------------------------------
__global__ void spec_finalize_kernel(float* __restrict__ out) {
    int t = threadIdx.x;
    int b = t >> 5;
    int k = (t >> 3) & 3;
    int l = t & 7;
    int row = ((k * DRAFT_LEN + l) << 3) + b;   // flattened (k,l,b)

    // per-batch exp-sum
    __shared__ float smsum[B_SIZE];
    if (t < B_SIZE) {
        float s = 0.0f;
        #pragma unroll
        for (int c = 0; c < SCHUNKS; c++) s += g_sumpart[t][c];
        smsum[t] = s;
    }

    // combine the 8 chunk partials of this row (chunks are ascending idx
    // ranges; strict > keeps the earliest chunk on exact ties)
    float bestE = g_pE[row * NCHUNKS];
    float beste = g_pe[row * NCHUNKS];
    int   tok   = g_pi[row * NCHUNKS];
    #pragma unroll
    for (int c = 1; c < NCHUNKS; c++) {
        float E2 = g_pE[row * NCHUNKS + c];
        float e2 = g_pe[row * NCHUNKS + c];
        if (E2 * beste > bestE * e2) {
            bestE = E2; beste = e2; tok = g_pi[row * NCHUNKS + c];
        }
    }
    __syncthreads();

    float p = g_E[b][tok] / smsum[b];
    float m = (p >= 0.8f) ? 1.0f : 0.0f;

    out[t]       = (float)tok;   // token ids < 2^24: exact in f32
    out[256 + t] = p;
    out[512 + t] = m;

    __shared__ float sp[256];
    __shared__ float sm[256];
    __shared__ float meanp[32];
    sp[t] = p; sm[t] = m;
    __syncthreads();

    if ((t & 7) == 0) {
        float ps = 0.0f, ms = 0.0f;
        #pragma unroll
        for (int i = 0; i < 8; i++) { ps += sp[t + i]; ms += sm[t + i]; }
        int bk = t >> 3;                 // = b*4 + k
        out[768 + bk] = ms * 0.125f;     // acceptance_ratio
        meanp[bk] = ps;                  // scale irrelevant to argmax
    }
    __syncthreads();

    if (t < B_SIZE) {
        float bv = meanp[t * 4];
        int bi = 0;
        #pragma unroll
        for (int kk = 1; kk < 4; kk++) {
            float vv = meanp[t * 4 + kk];
            if (vv > bv) { bv = vv; bi = kk; }   // strict >: first max wins
        }
        out[800 + t] = (float)bi;
    }
}

extern "C" void kernel_launch(void* const* d_in, const int* in_sizes, int n_in,
                              void* d_out, int out_size) {
    // metadata order: hidden_states, logits, verifier_logits.
    // Only logits[:, -1, :] is live in the reference.
    const float* logits = (const float*)d_in[1];
    float* out = (float*)d_out;

    spec_exp_kernel<<<dim3(B_SIZE, SCHUNKS), 256>>>(logits);
    spec_argmax_kernel<<<dim3(NCHUNKS, NROWS), 256>>>();
    spec_finalize_kernel<<<1, 256>>>(out);
}